// round 13
// baseline (speedup 1.0000x reference)
#include <cuda_runtime.h>

// Problem constants
#define N_    64
#define C_    64
#define T_    300
#define V_    25
#define IC_   16
#define NS_   3

typedef unsigned long long ull;

__device__ __forceinline__ ull dup2(float v) {
    ull r; asm("mov.b64 %0, {%1, %1};" : "=l"(r) : "f"(v)); return r;
}
__device__ __forceinline__ void fma2(ull& acc, ull a, ull b) {
    asm("fma.rn.f32x2 %0, %1, %2, %0;" : "+l"(acc) : "l"(a), "l"(b));
}
__device__ __forceinline__ void unpack2(ull v, float& lo, float& hi) {
    asm("mov.b64 {%0, %1}, %2;" : "=f"(lo), "=f"(hi) : "l"(v));
}

// Fast exp on the FMA pipe (no MUFU). |rel err| ~2e-6.
__device__ __forceinline__ float fastexp(float x) {
    const float L2E = 1.4426950408889634f;
    x = fmaxf(x, -80.0f);
    float t = fmaf(x, L2E, 12582912.0f);
    float k = t - 12582912.0f;
    float f = fmaf(x, L2E, -k);
    float p =              1.3333558146e-3f;
    p = fmaf(p, f, 9.6181291076e-3f);
    p = fmaf(p, f, 5.5504108664e-2f);
    p = fmaf(p, f, 2.4022650696e-1f);
    p = fmaf(p, f, 6.9314718056e-1f);
    p = fmaf(p, f, 1.0f);
    int ik = __float_as_int(t) - 0x4B400000;
    float scale = __int_as_float((ik + 127) << 23);
    return p * scale;
}

// Intermediate M buffer: M[s][n][t][v]
__device__ float g_M[NS_ * N_ * T_ * V_];

// ======================= Kernel A: attention -> M (persistent) =======================
#define TCA     4
#define COLSA   100
#define NTA     384                      // 12 warps = NS_ * TCA
#define NCHUNKA (N_ * (T_ / TCA))        // 4800
#define GRIDA_P 296                      // one wave: 148 SMs x 2

struct SmemA {
    float WabT[NS_][64][32];        // 24576 B  [s][c][r] r<16:a_w r>=16:b_w
    float xs[64][COLSA];            // 25600 B
    float CaCb[NS_][32][TCA * 28];  // 43008 B  [s][r][tc*28+v]
    float colA[NS_][32];
    float absh[NS_][32];
};

__global__ void __launch_bounds__(NTA, 2)
tsagc_attn_kernel(const float* __restrict__ x,
                  const float* __restrict__ A,
                  const float* __restrict__ GA,
                  const float* __restrict__ a_w,
                  const float* __restrict__ a_b,
                  const float* __restrict__ b_w,
                  const float* __restrict__ b_b)
{
    extern __shared__ float smem_raw[];
    SmemA& sm = *reinterpret_cast<SmemA*>(smem_raw);
    const int tid = threadIdx.x;

    // ---- stage weights / constants ONCE ----
    for (int idx = tid; idx < NS_ * IC_ * 64; idx += NTA) {
        int c  = idx & 63;
        int ic = (idx >> 6) & 15;
        int s  = idx >> 10;
        sm.WabT[s][c][ic]      = a_w[idx];
        sm.WabT[s][c][16 + ic] = b_w[idx];
    }
    for (int idx = tid; idx < NS_ * IC_; idx += NTA) {
        int s = idx / IC_, ic = idx % IC_;
        sm.absh[s][ic]      = a_b[idx];
        sm.absh[s][16 + ic] = b_b[idx];
    }
    for (int idx = tid; idx < NS_ * V_; idx += NTA) {
        int s = idx / V_, v = idx % V_;
        float acc = 0.f;
        #pragma unroll 5
        for (int a = 0; a < V_; a++) {
            int off = (s * V_ + a) * V_ + v;
            acc += A[off] + GA[off];
        }
        sm.colA[s][v] = acc;
    }
    // zero CaCb pad columns v=25..27 (all s) — phase 1 never overwrites them
    for (int idx = tid; idx < NS_ * 32 * TCA * 3; idx += NTA) {
        int s = idx / (32 * TCA * 3);
        int r = (idx / (TCA * 3)) % 32;
        int q = idx % (TCA * 3);
        sm.CaCb[s][r][(q / 3) * 28 + 25 + (q % 3)] = 0.f;
    }

    // thread mappings (chunk-invariant)
    const int s1p   = (tid < 300) ? tid / 100 : 0;
    const int rem1  = (tid < 300) ? tid - s1p * 100 : 0;
    const int rg1   = rem1 / 25;
    const int cg1   = rem1 % 25;
    const int col0  = cg1 * 4;
    const int r0    = rg1 * 8;
    int tcv[4], vv[4];
    #pragma unroll
    for (int j = 0; j < 4; j++) {
        int col = col0 + j;
        tcv[j] = col / 25;
        vv[j]  = col - tcv[j] * 25;
    }
    const int wid  = tid >> 5;
    const int lane = tid & 31;
    const int s2   = wid >> 2;
    const int tc2  = wid & 3;
    const int lv   = (lane < 25) ? lane : 0;
    const int cg2  = lv / 5;
    const int rg2  = lv % 5;
    const int a0   = rg2 * 5;
    const int b0   = cg2 * 5;
    const int tcBase2 = tc2 * 28;

    for (int chunk = blockIdx.x; chunk < NCHUNKA; chunk += GRIDA_P) {
        const int n  = chunk / (T_ / TCA);
        const int t0 = (chunk % (T_ / TCA)) * TCA;

        __syncthreads();   // staging done / previous chunk's phase-2 reads done

        // ---- load x chunk ----
        const float* xg = x + (n * 64 * T_ + t0) * V_;
        for (int idx = tid; idx < 64 * (COLSA / 4); idx += NTA) {
            int c = idx / (COLSA / 4), q = idx % (COLSA / 4);
            float4 val = *reinterpret_cast<const float4*>(xg + c * (T_ * V_) + q * 4);
            *reinterpret_cast<float4*>(&sm.xs[c][q * 4]) = val;
        }
        __syncthreads();

        // ---- Phase 1 (s-major): CaCb[s] = Wab[s] @ xs, 8 rows x 4 cols (300 thr) ----
        if (tid < 300) {
            ull acc2[4][4];   // [row-pair][col]
            #pragma unroll
            for (int k = 0; k < 4; k++)
                #pragma unroll
                for (int j = 0; j < 4; j++) acc2[k][j] = 0ull;

            #pragma unroll 2
            for (int c = 0; c < 64; c++) {
                ulonglong2 wp0 = *reinterpret_cast<const ulonglong2*>(&sm.WabT[s1p][c][r0]);
                ulonglong2 wp1 = *reinterpret_cast<const ulonglong2*>(&sm.WabT[s1p][c][r0 + 4]);
                float4 xv = *reinterpret_cast<const float4*>(&sm.xs[c][col0]);
                ull xd[4] = {dup2(xv.x), dup2(xv.y), dup2(xv.z), dup2(xv.w)};
                #pragma unroll
                for (int j = 0; j < 4; j++) {
                    fma2(acc2[0][j], wp0.x, xd[j]);
                    fma2(acc2[1][j], wp0.y, xd[j]);
                    fma2(acc2[2][j], wp1.x, xd[j]);
                    fma2(acc2[3][j], wp1.y, xd[j]);
                }
            }
            #pragma unroll
            for (int k = 0; k < 4; k++) {
                float bA = sm.absh[s1p][r0 + 2 * k];
                float bB = sm.absh[s1p][r0 + 2 * k + 1];
                #pragma unroll
                for (int j = 0; j < 4; j++) {
                    float lo, hi;
                    unpack2(acc2[k][j], lo, hi);
                    int off = tcv[j] * 28 + vv[j];
                    sm.CaCb[s1p][r0 + 2 * k][off]     = lo + bA;
                    sm.CaCb[s1p][r0 + 2 * k + 1][off] = hi + bB;
                }
            }
        }
        __syncthreads();

        // ---- Phase 2: one warp per (s,tc); 5x5 lane grid; no barriers ----
        {
            float S[5][5];
            #pragma unroll
            for (int i = 0; i < 5; i++)
                #pragma unroll
                for (int j = 0; j < 5; j++) S[i][j] = 0.f;

            #pragma unroll 4
            for (int ic = 0; ic < 16; ic++) {
                float ca[5], cb[5];
                #pragma unroll
                for (int i = 0; i < 5; i++)
                    ca[i] = sm.CaCb[s2][ic][tcBase2 + a0 + i];
                #pragma unroll
                for (int j = 0; j < 5; j++)
                    cb[j] = sm.CaCb[s2][16 + ic][tcBase2 + b0 + j];
                #pragma unroll
                for (int i = 0; i < 5; i++)
                    #pragma unroll
                    for (int j = 0; j < 5; j++) S[i][j] += ca[i] * cb[j];
            }

            float rmax[5];
            #pragma unroll
            for (int i = 0; i < 5; i++) {
                float m = -1e30f;
                #pragma unroll
                for (int j = 0; j < 5; j++) { S[i][j] *= 0.0625f; m = fmaxf(m, S[i][j]); }
                rmax[i] = m;
            }
            #pragma unroll
            for (int k = 1; k < 5; k++) {
                int src = ((cg2 + k) % 5) * 5 + rg2;
                #pragma unroll
                for (int i = 0; i < 5; i++)
                    rmax[i] = fmaxf(rmax[i], __shfl_sync(0xFFFFFFFFu, rmax[i], src));
            }

            float rsum[5];
            #pragma unroll
            for (int i = 0; i < 5; i++) {
                float ssum = 0.f;
                #pragma unroll
                for (int j = 0; j < 5; j++) {
                    float e = fastexp(S[i][j] - rmax[i]);
                    S[i][j] = e;
                    ssum += e;
                }
                rsum[i] = ssum;
            }
            #pragma unroll
            for (int k = 1; k < 5; k++) {
                int src = ((cg2 + k) % 5) * 5 + rg2;
                #pragma unroll
                for (int i = 0; i < 5; i++)
                    rsum[i] += __shfl_sync(0xFFFFFFFFu, rsum[i], src);
            }

            float colS[5];
            #pragma unroll
            for (int j = 0; j < 5; j++) colS[j] = 0.f;
            #pragma unroll
            for (int i = 0; i < 5; i++) {
                float rinv = 1.f / rsum[i];
                #pragma unroll
                for (int j = 0; j < 5; j++) colS[j] += S[i][j] * rinv;
            }
            #pragma unroll
            for (int k = 1; k < 5; k++) {
                int src = cg2 * 5 + (rg2 + k) % 5;
                #pragma unroll
                for (int j = 0; j < 5; j++)
                    colS[j] += __shfl_sync(0xFFFFFFFFu, colS[j], src);
            }

            if (lane < 25 && rg2 == 0) {
                float* mp = &g_M[((s2 * N_ + n) * T_ + t0 + tc2) * V_ + b0];
                #pragma unroll
                for (int j = 0; j < 5; j++)
                    mp[j] = colS[j] + sm.colA[s2][b0 + j];
            }
        }
    }
}

// ======================= Kernel B: output GEMM (persistent, per-block o-half) =======================
#define TCB     12
#define COLSB   300
#define NTB     300
#define NCHUNKB (N_ * (T_ / TCB))       // 1600 (n,t) chunks per o-half
#define GRIDB_P 296                     // one wave: 148 SMs x 2; half per parity

struct SmemB {
    float GTh[NS_][64][32];    // 24576 B  [s][c][o_local], this block's o-half
    float xs[64][COLSB];       // 76800 B
    float Msm[NS_][COLSB];     // 3600 B
    float scArr[32];
    float shArr[32];
};

__global__ void __launch_bounds__(NTB, 2)
tsagc_out_kernel(const float* __restrict__ x,
                 const float* __restrict__ g_w,
                 const float* __restrict__ g_b,
                 const float* __restrict__ bn_gamma,
                 const float* __restrict__ bn_beta,
                 const float* __restrict__ bn_mean,
                 const float* __restrict__ bn_var,
                 float* __restrict__ out)
{
    extern __shared__ float smem_raw[];
    SmemB& sm = *reinterpret_cast<SmemB*>(smem_raw);
    const int tid = threadIdx.x;

    const int o_base = (blockIdx.x & 1) * 32;   // block owns one o-half forever

    // ---- stage this half's GT + BN constants ONCE ----
    for (int idx = tid; idx < NS_ * 64 * 32; idx += NTB) {
        int ol = idx & 31;
        int c  = (idx >> 5) & 63;
        int s  = idx >> 11;
        sm.GTh[s][c][ol] = g_w[(s * 64 + o_base + ol) * 64 + c];
    }
    if (tid < 32) {
        int o = o_base + tid;
        float inv = rsqrtf(bn_var[o] + 1e-5f);
        float scv = bn_gamma[o] * inv;
        sm.scArr[tid] = scv;
        float cb = g_b[o] + g_b[64 + o] + g_b[128 + o];
        sm.shArr[tid] = (cb - bn_mean[o]) * scv + bn_beta[o];
    }

    // chunk-invariant thread mapping
    const int rg   = tid / 75;     // 0..3 -> o0 local = rg*8
    const int cg   = tid % 75;     // 0..74
    const int col0 = cg * 4;
    const int o0   = rg * 8;

    for (int chunk = (blockIdx.x >> 1); chunk < NCHUNKB; chunk += (GRIDB_P >> 1)) {
        const int n  = chunk / (T_ / TCB);
        const int t0 = (chunk % (T_ / TCB)) * TCB;

        __syncthreads();   // staging done / previous epilogue xs reads done

        // ---- load x chunk + M chunk ----
        const float* xg = x + (n * 64 * T_ + t0) * V_;
        for (int idx = tid; idx < 64 * (COLSB / 4); idx += NTB) {
            int c = idx / (COLSB / 4), q = idx % (COLSB / 4);
            float4 val = *reinterpret_cast<const float4*>(xg + c * (T_ * V_) + q * 4);
            *reinterpret_cast<float4*>(&sm.xs[c][q * 4]) = val;
        }
        for (int idx = tid; idx < NS_ * (COLSB / 4); idx += NTB) {
            int s = idx / (COLSB / 4), q = idx % (COLSB / 4);
            float4 val = *reinterpret_cast<const float4*>(
                &g_M[(s * N_ + n) * (T_ * V_) + t0 * V_ + q * 4]);
            *reinterpret_cast<float4*>(&sm.Msm[s][q * 4]) = val;
        }
        __syncthreads();

        // ---- mainloop: 8 rows (4 o-pairs) x 4 cols per thread, fused s ----
        float ms[NS_][4];
        #pragma unroll
        for (int s = 0; s < NS_; s++)
            #pragma unroll
            for (int j = 0; j < 4; j++) ms[s][j] = sm.Msm[s][col0 + j];

        ull acc2[4][4];   // [o-pair][col]
        #pragma unroll
        for (int k = 0; k < 4; k++)
            #pragma unroll
            for (int j = 0; j < 4; j++) acc2[k][j] = 0ull;

        #pragma unroll 2
        for (int c = 0; c < 64; c++) {
            float4 xv = *reinterpret_cast<const float4*>(&sm.xs[c][col0]);
            float xa[4] = {xv.x, xv.y, xv.z, xv.w};
            #pragma unroll
            for (int s = 0; s < NS_; s++) {
                const ulonglong2* gp =
                    reinterpret_cast<const ulonglong2*>(&sm.GTh[s][c][o0]);
                ulonglong2 g01 = gp[0];
                ulonglong2 g23 = gp[1];
                ull xm[4];
                #pragma unroll
                for (int j = 0; j < 4; j++) xm[j] = dup2(xa[j] * ms[s][j]);
                #pragma unroll
                for (int j = 0; j < 4; j++) {
                    fma2(acc2[0][j], g01.x, xm[j]);
                    fma2(acc2[1][j], g01.y, xm[j]);
                    fma2(acc2[2][j], g23.x, xm[j]);
                    fma2(acc2[3][j], g23.y, xm[j]);
                }
            }
        }

        // ---- epilogue: BN + residual + ReLU, float4 stores ----
        #pragma unroll
        for (int k = 0; k < 4; k++) {
            int oa = o0 + 2 * k;       // local
            int ob = oa + 1;
            float scA = sm.scArr[oa], shA = sm.shArr[oa];
            float scB = sm.scArr[ob], shB = sm.shArr[ob];
            float ra[4], rb[4];
            #pragma unroll
            for (int j = 0; j < 4; j++) unpack2(acc2[k][j], ra[j], rb[j]);
            float4 xrA = *reinterpret_cast<const float4*>(&sm.xs[o_base + oa][col0]);
            float4 xrB = *reinterpret_cast<const float4*>(&sm.xs[o_base + ob][col0]);
            float4 resA, resB;
            resA.x = fmaxf(ra[0] * scA + shA + xrA.x, 0.f);
            resA.y = fmaxf(ra[1] * scA + shA + xrA.y, 0.f);
            resA.z = fmaxf(ra[2] * scA + shA + xrA.z, 0.f);
            resA.w = fmaxf(ra[3] * scA + shA + xrA.w, 0.f);
            resB.x = fmaxf(rb[0] * scB + shB + xrB.x, 0.f);
            resB.y = fmaxf(rb[1] * scB + shB + xrB.y, 0.f);
            resB.z = fmaxf(rb[2] * scB + shB + xrB.z, 0.f);
            resB.w = fmaxf(rb[3] * scB + shB + xrB.w, 0.f);
            float* opA = out + (n * 64 + o_base + oa) * (T_ * V_) + t0 * V_ + col0;
            float* opB = out + (n * 64 + o_base + ob) * (T_ * V_) + t0 * V_ + col0;
            *reinterpret_cast<float4*>(opA) = resA;
            *reinterpret_cast<float4*>(opB) = resB;
        }
    }
}

extern "C" void kernel_launch(void* const* d_in, const int* in_sizes, int n_in,
                              void* d_out, int out_size)
{
    const float* x        = (const float*)d_in[0];
    const float* A        = (const float*)d_in[1];
    const float* GA       = (const float*)d_in[2];
    const float* g_w      = (const float*)d_in[3];
    const float* g_b      = (const float*)d_in[4];
    const float* a_w      = (const float*)d_in[5];
    const float* a_b      = (const float*)d_in[6];
    const float* b_w      = (const float*)d_in[7];
    const float* b_b      = (const float*)d_in[8];
    const float* bn_gamma = (const float*)d_in[9];
    const float* bn_beta  = (const float*)d_in[10];
    const float* bn_mean  = (const float*)d_in[11];
    const float* bn_var   = (const float*)d_in[12];
    float* out = (float*)d_out;

    size_t smemA = sizeof(SmemA);
    size_t smemB = sizeof(SmemB);
    cudaFuncSetAttribute(tsagc_attn_kernel,
                         cudaFuncAttributeMaxDynamicSharedMemorySize, (int)smemA);
    cudaFuncSetAttribute(tsagc_out_kernel,
                         cudaFuncAttributeMaxDynamicSharedMemorySize, (int)smemB);

    tsagc_attn_kernel<<<GRIDA_P, NTA, smemA>>>(x, A, GA, a_w, a_b, b_w, b_b);
    tsagc_out_kernel<<<GRIDB_P, NTB, smemB>>>(x, g_w, g_b, bn_gamma, bn_beta,
                                              bn_mean, bn_var, out);
}

// round 14
// speedup vs baseline: 1.6198x; 1.6198x over previous
#include <cuda_runtime.h>

// Problem constants
#define N_    64
#define C_    64
#define T_    300
#define V_    25
#define IC_   16
#define NS_   3

typedef unsigned long long ull;

__device__ __forceinline__ ull dup2(float v) {
    ull r; asm("mov.b64 %0, {%1, %1};" : "=l"(r) : "f"(v)); return r;
}
__device__ __forceinline__ void fma2(ull& acc, ull a, ull b) {
    asm("fma.rn.f32x2 %0, %1, %2, %0;" : "+l"(acc) : "l"(a), "l"(b));
}
__device__ __forceinline__ void unpack2(ull v, float& lo, float& hi) {
    asm("mov.b64 {%0, %1}, %2;" : "=f"(lo), "=f"(hi) : "l"(v));
}

// Fast exp on the FMA pipe (no MUFU). |rel err| ~2e-6.
__device__ __forceinline__ float fastexp(float x) {
    const float L2E = 1.4426950408889634f;
    x = fmaxf(x, -80.0f);
    float t = fmaf(x, L2E, 12582912.0f);
    float k = t - 12582912.0f;
    float f = fmaf(x, L2E, -k);
    float p =              1.3333558146e-3f;
    p = fmaf(p, f, 9.6181291076e-3f);
    p = fmaf(p, f, 5.5504108664e-2f);
    p = fmaf(p, f, 2.4022650696e-1f);
    p = fmaf(p, f, 6.9314718056e-1f);
    p = fmaf(p, f, 1.0f);
    int ik = __float_as_int(t) - 0x4B400000;
    float scale = __int_as_float((ik + 127) << 23);
    return p * scale;
}

// Intermediate M buffer: M[s][n][t][v]
__device__ float g_M[NS_ * N_ * T_ * V_];

// ======================= Kernel A: attention -> M (persistent) =======================
#define TCA     4
#define COLSA   100
#define NTA     384                      // 12 warps = NS_ * TCA
#define NCHUNKA (N_ * (T_ / TCA))        // 4800
#define GRIDA_P 296                      // one wave: 148 SMs x 2

struct SmemA {
    float WabT[NS_][64][32];        // 24576 B  [s][c][r] r<16:a_w r>=16:b_w
    float xs[64][COLSA];            // 25600 B
    float CaCb[NS_][32][TCA * 28];  // 43008 B  [s][r][tc*28+v]
    float colA[NS_][32];
    float absh[NS_][32];
};

__global__ void __launch_bounds__(NTA, 2)
tsagc_attn_kernel(const float* __restrict__ x,
                  const float* __restrict__ A,
                  const float* __restrict__ GA,
                  const float* __restrict__ a_w,
                  const float* __restrict__ a_b,
                  const float* __restrict__ b_w,
                  const float* __restrict__ b_b)
{
    extern __shared__ float smem_raw[];
    SmemA& sm = *reinterpret_cast<SmemA*>(smem_raw);
    const int tid = threadIdx.x;

    // ---- stage weights / constants ONCE ----
    for (int idx = tid; idx < NS_ * IC_ * 64; idx += NTA) {
        int c  = idx & 63;
        int ic = (idx >> 6) & 15;
        int s  = idx >> 10;
        sm.WabT[s][c][ic]      = a_w[idx];
        sm.WabT[s][c][16 + ic] = b_w[idx];
    }
    for (int idx = tid; idx < NS_ * IC_; idx += NTA) {
        int s = idx / IC_, ic = idx % IC_;
        sm.absh[s][ic]      = a_b[idx];
        sm.absh[s][16 + ic] = b_b[idx];
    }
    for (int idx = tid; idx < NS_ * V_; idx += NTA) {
        int s = idx / V_, v = idx % V_;
        float acc = 0.f;
        #pragma unroll 5
        for (int a = 0; a < V_; a++) {
            int off = (s * V_ + a) * V_ + v;
            acc += A[off] + GA[off];
        }
        sm.colA[s][v] = acc;
    }
    // zero CaCb pad columns v=25..27 (all s) — phase 1 never overwrites them
    for (int idx = tid; idx < NS_ * 32 * TCA * 3; idx += NTA) {
        int s = idx / (32 * TCA * 3);
        int r = (idx / (TCA * 3)) % 32;
        int q = idx % (TCA * 3);
        sm.CaCb[s][r][(q / 3) * 28 + 25 + (q % 3)] = 0.f;
    }

    // thread mappings (chunk-invariant)
    const int s1p   = (tid < 300) ? tid / 100 : 0;
    const int rem1  = (tid < 300) ? tid - s1p * 100 : 0;
    const int rg1   = rem1 / 25;
    const int cg1   = rem1 % 25;
    const int col0  = cg1 * 4;
    const int r0    = rg1 * 8;
    int tcv[4], vv[4];
    #pragma unroll
    for (int j = 0; j < 4; j++) {
        int col = col0 + j;
        tcv[j] = col / 25;
        vv[j]  = col - tcv[j] * 25;
    }
    const int wid  = tid >> 5;
    const int lane = tid & 31;
    const int s2   = wid >> 2;
    const int tc2  = wid & 3;
    const int lv   = (lane < 25) ? lane : 0;
    const int cg2  = lv / 5;
    const int rg2  = lv % 5;
    const int a0   = rg2 * 5;
    const int b0   = cg2 * 5;
    const int tcBase2 = tc2 * 28;

    for (int chunk = blockIdx.x; chunk < NCHUNKA; chunk += GRIDA_P) {
        const int n  = chunk / (T_ / TCA);
        const int t0 = (chunk % (T_ / TCA)) * TCA;

        __syncthreads();   // staging done / previous chunk's phase-2 reads done

        // ---- load x chunk ----
        const float* xg = x + (n * 64 * T_ + t0) * V_;
        for (int idx = tid; idx < 64 * (COLSA / 4); idx += NTA) {
            int c = idx / (COLSA / 4), q = idx % (COLSA / 4);
            float4 val = *reinterpret_cast<const float4*>(xg + c * (T_ * V_) + q * 4);
            *reinterpret_cast<float4*>(&sm.xs[c][q * 4]) = val;
        }
        __syncthreads();

        // ---- Phase 1 (s-major): CaCb[s] = Wab[s] @ xs, 8 rows x 4 cols (300 thr) ----
        if (tid < 300) {
            ull acc2[4][4];   // [row-pair][col]
            #pragma unroll
            for (int k = 0; k < 4; k++)
                #pragma unroll
                for (int j = 0; j < 4; j++) acc2[k][j] = 0ull;

            #pragma unroll 2
            for (int c = 0; c < 64; c++) {
                ulonglong2 wp0 = *reinterpret_cast<const ulonglong2*>(&sm.WabT[s1p][c][r0]);
                ulonglong2 wp1 = *reinterpret_cast<const ulonglong2*>(&sm.WabT[s1p][c][r0 + 4]);
                float4 xv = *reinterpret_cast<const float4*>(&sm.xs[c][col0]);
                ull xd[4] = {dup2(xv.x), dup2(xv.y), dup2(xv.z), dup2(xv.w)};
                #pragma unroll
                for (int j = 0; j < 4; j++) {
                    fma2(acc2[0][j], wp0.x, xd[j]);
                    fma2(acc2[1][j], wp0.y, xd[j]);
                    fma2(acc2[2][j], wp1.x, xd[j]);
                    fma2(acc2[3][j], wp1.y, xd[j]);
                }
            }
            #pragma unroll
            for (int k = 0; k < 4; k++) {
                float bA = sm.absh[s1p][r0 + 2 * k];
                float bB = sm.absh[s1p][r0 + 2 * k + 1];
                #pragma unroll
                for (int j = 0; j < 4; j++) {
                    float lo, hi;
                    unpack2(acc2[k][j], lo, hi);
                    int off = tcv[j] * 28 + vv[j];
                    sm.CaCb[s1p][r0 + 2 * k][off]     = lo + bA;
                    sm.CaCb[s1p][r0 + 2 * k + 1][off] = hi + bB;
                }
            }
        }
        __syncthreads();

        // ---- Phase 2: one warp per (s,tc); 5x5 lane grid; no barriers ----
        {
            float S[5][5];
            #pragma unroll
            for (int i = 0; i < 5; i++)
                #pragma unroll
                for (int j = 0; j < 5; j++) S[i][j] = 0.f;

            #pragma unroll 4
            for (int ic = 0; ic < 16; ic++) {
                float ca[5], cb[5];
                #pragma unroll
                for (int i = 0; i < 5; i++)
                    ca[i] = sm.CaCb[s2][ic][tcBase2 + a0 + i];
                #pragma unroll
                for (int j = 0; j < 5; j++)
                    cb[j] = sm.CaCb[s2][16 + ic][tcBase2 + b0 + j];
                #pragma unroll
                for (int i = 0; i < 5; i++)
                    #pragma unroll
                    for (int j = 0; j < 5; j++) S[i][j] += ca[i] * cb[j];
            }

            float rmax[5];
            #pragma unroll
            for (int i = 0; i < 5; i++) {
                float m = -1e30f;
                #pragma unroll
                for (int j = 0; j < 5; j++) { S[i][j] *= 0.0625f; m = fmaxf(m, S[i][j]); }
                rmax[i] = m;
            }
            #pragma unroll
            for (int k = 1; k < 5; k++) {
                int src = ((cg2 + k) % 5) * 5 + rg2;
                #pragma unroll
                for (int i = 0; i < 5; i++)
                    rmax[i] = fmaxf(rmax[i], __shfl_sync(0xFFFFFFFFu, rmax[i], src));
            }

            float rsum[5];
            #pragma unroll
            for (int i = 0; i < 5; i++) {
                float ssum = 0.f;
                #pragma unroll
                for (int j = 0; j < 5; j++) {
                    float e = fastexp(S[i][j] - rmax[i]);
                    S[i][j] = e;
                    ssum += e;
                }
                rsum[i] = ssum;
            }
            #pragma unroll
            for (int k = 1; k < 5; k++) {
                int src = ((cg2 + k) % 5) * 5 + rg2;
                #pragma unroll
                for (int i = 0; i < 5; i++)
                    rsum[i] += __shfl_sync(0xFFFFFFFFu, rsum[i], src);
            }

            float colS[5];
            #pragma unroll
            for (int j = 0; j < 5; j++) colS[j] = 0.f;
            #pragma unroll
            for (int i = 0; i < 5; i++) {
                float rinv = 1.f / rsum[i];
                #pragma unroll
                for (int j = 0; j < 5; j++) colS[j] += S[i][j] * rinv;
            }
            #pragma unroll
            for (int k = 1; k < 5; k++) {
                int src = cg2 * 5 + (rg2 + k) % 5;
                #pragma unroll
                for (int j = 0; j < 5; j++)
                    colS[j] += __shfl_sync(0xFFFFFFFFu, colS[j], src);
            }

            if (lane < 25 && rg2 == 0) {
                float* mp = &g_M[((s2 * N_ + n) * T_ + t0 + tc2) * V_ + b0];
                #pragma unroll
                for (int j = 0; j < 5; j++)
                    mp[j] = colS[j] + sm.colA[s2][b0 + j];
            }
        }
    }
}

// ======================= Kernel B: output GEMM (o-split, non-persistent, R10 config) ===========
#define TCB   12
#define COLSB 300
#define NTB   300
#define GRIDB (N_ * (T_ / TCB) * 2)   // 3200

struct SmemB {
    float GTh[NS_][64][32];    // 24576 B  [s][c][o_local], o-half
    float xs[64][COLSB];       // 76800 B
    float Msm[NS_][COLSB];     // 3600 B
    float scArr[32];
    float shArr[32];
};

__global__ void __launch_bounds__(NTB, 2)
tsagc_out_kernel(const float* __restrict__ x,
                 const float* __restrict__ g_w,
                 const float* __restrict__ g_b,
                 const float* __restrict__ bn_gamma,
                 const float* __restrict__ bn_beta,
                 const float* __restrict__ bn_mean,
                 const float* __restrict__ bn_var,
                 float* __restrict__ out)
{
    extern __shared__ float smem_raw[];
    SmemB& sm = *reinterpret_cast<SmemB*>(smem_raw);
    const int tid = threadIdx.x;

    const int bid    = blockIdx.x;
    const int n      = bid / (2 * (T_ / TCB));
    const int rem    = bid % (2 * (T_ / TCB));
    const int t0     = (rem >> 1) * TCB;
    const int o_base = (rem & 1) * 32;

    // ---- stage GT half (transposed) ----
    for (int idx = tid; idx < NS_ * 64 * 32; idx += NTB) {
        int ol = idx & 31;
        int c  = (idx >> 5) & 63;
        int s  = idx >> 11;
        sm.GTh[s][c][ol] = g_w[(s * 64 + o_base + ol) * 64 + c];
    }
    if (tid < 32) {
        int o = o_base + tid;
        float inv = rsqrtf(bn_var[o] + 1e-5f);
        float scv = bn_gamma[o] * inv;
        sm.scArr[tid] = scv;
        float cb = g_b[o] + g_b[64 + o] + g_b[128 + o];
        sm.shArr[tid] = (cb - bn_mean[o]) * scv + bn_beta[o];
    }

    // ---- load x chunk + M chunk ----
    const float* xg = x + (n * 64 * T_ + t0) * V_;
    for (int idx = tid; idx < 64 * (COLSB / 4); idx += NTB) {
        int c = idx / (COLSB / 4), q = idx % (COLSB / 4);
        float4 val = *reinterpret_cast<const float4*>(xg + c * (T_ * V_) + q * 4);
        *reinterpret_cast<float4*>(&sm.xs[c][q * 4]) = val;
    }
    for (int idx = tid; idx < NS_ * (COLSB / 4); idx += NTB) {
        int s = idx / (COLSB / 4), q = idx % (COLSB / 4);
        float4 val = *reinterpret_cast<const float4*>(
            &g_M[(s * N_ + n) * (T_ * V_) + t0 * V_ + q * 4]);
        *reinterpret_cast<float4*>(&sm.Msm[s][q * 4]) = val;
    }
    __syncthreads();

    // ---- mainloop: 8 rows (4 o-pairs) x 4 cols per thread, fused s ----
    const int rg   = tid / 75;     // 0..3 -> o0 local = rg*8
    const int cg   = tid % 75;     // 0..74
    const int col0 = cg * 4;
    const int o0   = rg * 8;

    float ms[NS_][4];
    #pragma unroll
    for (int s = 0; s < NS_; s++)
        #pragma unroll
        for (int j = 0; j < 4; j++) ms[s][j] = sm.Msm[s][col0 + j];

    ull acc2[4][4];   // [o-pair][col]
    #pragma unroll
    for (int k = 0; k < 4; k++)
        #pragma unroll
        for (int j = 0; j < 4; j++) acc2[k][j] = 0ull;

    #pragma unroll 2
    for (int c = 0; c < 64; c++) {
        float4 xv = *reinterpret_cast<const float4*>(&sm.xs[c][col0]);
        float xa[4] = {xv.x, xv.y, xv.z, xv.w};
        #pragma unroll
        for (int s = 0; s < NS_; s++) {
            const ulonglong2* gp =
                reinterpret_cast<const ulonglong2*>(&sm.GTh[s][c][o0]);
            ulonglong2 g01 = gp[0];
            ulonglong2 g23 = gp[1];
            ull xm[4];
            #pragma unroll
            for (int j = 0; j < 4; j++) xm[j] = dup2(xa[j] * ms[s][j]);
            #pragma unroll
            for (int j = 0; j < 4; j++) {
                fma2(acc2[0][j], g01.x, xm[j]);
                fma2(acc2[1][j], g01.y, xm[j]);
                fma2(acc2[2][j], g23.x, xm[j]);
                fma2(acc2[3][j], g23.y, xm[j]);
            }
        }
    }

    // ---- epilogue: BN + residual + ReLU, float4 stores ----
    #pragma unroll
    for (int k = 0; k < 4; k++) {
        int oa = o0 + 2 * k;       // local
        int ob = oa + 1;
        float scA = sm.scArr[oa], shA = sm.shArr[oa];
        float scB = sm.scArr[ob], shB = sm.shArr[ob];
        float ra[4], rb[4];
        #pragma unroll
        for (int j = 0; j < 4; j++) unpack2(acc2[k][j], ra[j], rb[j]);
        float4 xrA = *reinterpret_cast<const float4*>(&sm.xs[o_base + oa][col0]);
        float4 xrB = *reinterpret_cast<const float4*>(&sm.xs[o_base + ob][col0]);
        float4 resA, resB;
        resA.x = fmaxf(ra[0] * scA + shA + xrA.x, 0.f);
        resA.y = fmaxf(ra[1] * scA + shA + xrA.y, 0.f);
        resA.z = fmaxf(ra[2] * scA + shA + xrA.z, 0.f);
        resA.w = fmaxf(ra[3] * scA + shA + xrA.w, 0.f);
        resB.x = fmaxf(rb[0] * scB + shB + xrB.x, 0.f);
        resB.y = fmaxf(rb[1] * scB + shB + xrB.y, 0.f);
        resB.z = fmaxf(rb[2] * scB + shB + xrB.z, 0.f);
        resB.w = fmaxf(rb[3] * scB + shB + xrB.w, 0.f);
        float* opA = out + (n * 64 + o_base + oa) * (T_ * V_) + t0 * V_ + col0;
        float* opB = out + (n * 64 + o_base + ob) * (T_ * V_) + t0 * V_ + col0;
        *reinterpret_cast<float4*>(opA) = resA;
        *reinterpret_cast<float4*>(opB) = resB;
    }
}

extern "C" void kernel_launch(void* const* d_in, const int* in_sizes, int n_in,
                              void* d_out, int out_size)
{
    const float* x        = (const float*)d_in[0];
    const float* A        = (const float*)d_in[1];
    const float* GA       = (const float*)d_in[2];
    const float* g_w      = (const float*)d_in[3];
    const float* g_b      = (const float*)d_in[4];
    const float* a_w      = (const float*)d_in[5];
    const float* a_b      = (const float*)d_in[6];
    const float* b_w      = (const float*)d_in[7];
    const float* b_b      = (const float*)d_in[8];
    const float* bn_gamma = (const float*)d_in[9];
    const float* bn_beta  = (const float*)d_in[10];
    const float* bn_mean  = (const float*)d_in[11];
    const float* bn_var   = (const float*)d_in[12];
    float* out = (float*)d_out;

    size_t smemA = sizeof(SmemA);
    size_t smemB = sizeof(SmemB);
    cudaFuncSetAttribute(tsagc_attn_kernel,
                         cudaFuncAttributeMaxDynamicSharedMemorySize, (int)smemA);
    cudaFuncSetAttribute(tsagc_out_kernel,
                         cudaFuncAttributeMaxDynamicSharedMemorySize, (int)smemB);

    tsagc_attn_kernel<<<GRIDA_P, NTA, smemA>>>(x, A, GA, a_w, a_b, b_w, b_b);
    tsagc_out_kernel<<<GRIDB, NTB, smemB>>>(x, g_w, g_b, bn_gamma, bn_beta,
                                            bn_mean, bn_var, out);
}

// round 16
// speedup vs baseline: 1.7384x; 1.0732x over previous
#include <cuda_runtime.h>

// Problem constants
#define N_    64
#define C_    64
#define T_    300
#define V_    25
#define IC_   16
#define NS_   3

typedef unsigned long long ull;

__device__ __forceinline__ ull dup2(float v) {
    ull r; asm("mov.b64 %0, {%1, %1};" : "=l"(r) : "f"(v)); return r;
}
__device__ __forceinline__ void fma2(ull& acc, ull a, ull b) {
    asm("fma.rn.f32x2 %0, %1, %2, %0;" : "+l"(acc) : "l"(a), "l"(b));
}
__device__ __forceinline__ void unpack2(ull v, float& lo, float& hi) {
    asm("mov.b64 {%0, %1}, %2;" : "=f"(lo), "=f"(hi) : "l"(v));
}

// Fast exp on the FMA pipe (no MUFU). |rel err| ~2e-6.
__device__ __forceinline__ float fastexp(float x) {
    const float L2E = 1.4426950408889634f;
    x = fmaxf(x, -80.0f);
    float t = fmaf(x, L2E, 12582912.0f);
    float k = t - 12582912.0f;
    float f = fmaf(x, L2E, -k);
    float p =              1.3333558146e-3f;
    p = fmaf(p, f, 9.6181291076e-3f);
    p = fmaf(p, f, 5.5504108664e-2f);
    p = fmaf(p, f, 2.4022650696e-1f);
    p = fmaf(p, f, 6.9314718056e-1f);
    p = fmaf(p, f, 1.0f);
    int ik = __float_as_int(t) - 0x4B400000;
    float scale = __int_as_float((ik + 127) << 23);
    return p * scale;
}

#define TCHUNK  12                      // t per fused chunk
#define COLS    300                     // TCHUNK * V_
#define TSUB    4                       // t per attention sub-chunk
#define SUBCOLS 100
#define NT      384                     // 12 warps
#define NCHUNK  (N_ * (T_ / TCHUNK))    // 1600
#define GRID_P  148                     // 1 block per SM, persistent

struct SmemF {
    float WabT[NS_][64][32];        // 24576 B  [s][c][r] r<16:a_w r>=16:b_w
    float GT[NS_][64][64];          // 49152 B  [s][c][o]
    float xs[64][COLS];             // 76800 B
    float CaCb[NS_][32][TSUB * 28]; // 43008 B  [s][r][tc*28+v]
    float Msm[NS_][COLS];           //  3600 B
    float colA[NS_][32];
    float absh[NS_][32];
    float scArr[64];
    float shArr[64];
};   // ~198 KB

__global__ void __launch_bounds__(NT, 1)
tsagc_fused_kernel(const float* __restrict__ x,
                   const float* __restrict__ A,
                   const float* __restrict__ GA,
                   const float* __restrict__ g_w,
                   const float* __restrict__ g_b,
                   const float* __restrict__ a_w,
                   const float* __restrict__ a_b,
                   const float* __restrict__ b_w,
                   const float* __restrict__ b_b,
                   const float* __restrict__ bn_gamma,
                   const float* __restrict__ bn_beta,
                   const float* __restrict__ bn_mean,
                   const float* __restrict__ bn_var,
                   float* __restrict__ out)
{
    extern __shared__ float smem_raw[];
    SmemF& sm = *reinterpret_cast<SmemF*>(smem_raw);
    const int tid = threadIdx.x;

    // ================= one-time staging =================
    for (int idx = tid; idx < NS_ * IC_ * 64; idx += NT) {
        int c  = idx & 63;
        int ic = (idx >> 6) & 15;
        int s  = idx >> 10;
        sm.WabT[s][c][ic]      = a_w[idx];
        sm.WabT[s][c][16 + ic] = b_w[idx];
    }
    for (int idx = tid; idx < NS_ * 64 * 64; idx += NT) {
        int c = idx & 63;
        int o = (idx >> 6) & 63;
        int s = idx >> 12;
        sm.GT[s][c][o] = g_w[idx];
    }
    if (tid < 64) {
        float inv = rsqrtf(bn_var[tid] + 1e-5f);
        float scv = bn_gamma[tid] * inv;
        sm.scArr[tid] = scv;
        float cb = g_b[tid] + g_b[64 + tid] + g_b[128 + tid];
        sm.shArr[tid] = (cb - bn_mean[tid]) * scv + bn_beta[tid];
    }
    for (int idx = tid; idx < NS_ * IC_; idx += NT) {
        int s = idx / IC_, ic = idx % IC_;
        sm.absh[s][ic]      = a_b[idx];
        sm.absh[s][16 + ic] = b_b[idx];
    }
    for (int idx = tid; idx < NS_ * V_; idx += NT) {
        int s = idx / V_, v = idx % V_;
        float acc = 0.f;
        #pragma unroll 5
        for (int a = 0; a < V_; a++) {
            int off = (s * V_ + a) * V_ + v;
            acc += A[off] + GA[off];
        }
        sm.colA[s][v] = acc;
    }
    // zero CaCb pad columns v=25..27 (phase 1 never overwrites them)
    for (int idx = tid; idx < NS_ * 32 * TSUB * 3; idx += NT) {
        int s = idx / (32 * TSUB * 3);
        int r = (idx / (TSUB * 3)) % 32;
        int q = idx % (TSUB * 3);
        sm.CaCb[s][r][(q / 3) * 28 + 25 + (q % 3)] = 0.f;
    }

    // ================= chunk-invariant mappings =================
    // phase-1 (tid < 300): s-major 8 rows x 4 cols (within a 100-col sub-chunk)
    const int s1p  = (tid < 300) ? tid / 100 : 0;
    const int rem1 = (tid < 300) ? tid - s1p * 100 : 0;
    const int rg1  = rem1 / 25;
    const int cg1  = rem1 % 25;
    const int p1c0 = cg1 * 4;
    const int r0   = rg1 * 8;
    int tcv[4], vv[4];
    #pragma unroll
    for (int j = 0; j < 4; j++) {
        int col = p1c0 + j;
        tcv[j] = col / 25;
        vv[j]  = col - tcv[j] * 25;
    }
    // phase-2: warp = (s,tc); 5x5 lane grid
    const int wid  = tid >> 5;
    const int lane = tid & 31;
    const int s2   = wid >> 2;
    const int tc2  = wid & 3;
    const int lv   = (lane < 25) ? lane : 0;
    const int cg2  = lv / 5;
    const int rg2  = lv % 5;
    const int a0   = rg2 * 5;
    const int b0   = cg2 * 5;
    const int tcBase2 = tc2 * 28;
    // B-main (tid < 300): 16 rows x 4 cols over full o
    const int rgB  = tid / 75;          // 0..3 -> o0 = rgB*16
    const int cgB  = tid % 75;          // 0..74
    const int colB = cgB * 4;
    const int o0   = rgB * 16;

    // ================= persistent chunk loop =================
    for (int chunk = blockIdx.x; chunk < NCHUNK; chunk += GRID_P) {
        const int n   = chunk / (T_ / TCHUNK);
        const int t12 = (chunk % (T_ / TCHUNK)) * TCHUNK;

        // prefetch x into registers (gmem reads; no smem conflict with prev chunk)
        const float* xg = x + (n * 64 * T_ + t12) * V_;
        float4 xpre[13];
        #pragma unroll
        for (int k = 0; k < 13; k++) {
            int idx = tid + k * NT;
            if (idx < 4800) {
                int c = idx / 75, q = idx % 75;
                xpre[k] = *reinterpret_cast<const float4*>(xg + c * (T_ * V_) + q * 4);
            }
        }

        __syncthreads();   // prev chunk's xs/Msm readers done

        #pragma unroll
        for (int k = 0; k < 13; k++) {
            int idx = tid + k * NT;
            if (idx < 4800) {
                int c = idx / 75, q = idx % 75;
                *reinterpret_cast<float4*>(&sm.xs[c][q * 4]) = xpre[k];
            }
        }

        // ---------- attention sub-chunks ----------
        for (int sc = 0; sc < 3; sc++) {
            __syncthreads();   // xs ready / prev phase-2 CaCb reads done

            // Phase 1: CaCb[s] = Wab[s] @ xs[:, sc*100 ..], 8x4 tiles
            if (tid < 300) {
                ull acc2[4][4];
                #pragma unroll
                for (int k = 0; k < 4; k++)
                    #pragma unroll
                    for (int j = 0; j < 4; j++) acc2[k][j] = 0ull;

                const int xoff = sc * SUBCOLS + p1c0;
                #pragma unroll 2
                for (int c = 0; c < 64; c++) {
                    ulonglong2 wp0 = *reinterpret_cast<const ulonglong2*>(&sm.WabT[s1p][c][r0]);
                    ulonglong2 wp1 = *reinterpret_cast<const ulonglong2*>(&sm.WabT[s1p][c][r0 + 4]);
                    float4 xv = *reinterpret_cast<const float4*>(&sm.xs[c][xoff]);
                    ull xd[4] = {dup2(xv.x), dup2(xv.y), dup2(xv.z), dup2(xv.w)};
                    #pragma unroll
                    for (int j = 0; j < 4; j++) {
                        fma2(acc2[0][j], wp0.x, xd[j]);
                        fma2(acc2[1][j], wp0.y, xd[j]);
                        fma2(acc2[2][j], wp1.x, xd[j]);
                        fma2(acc2[3][j], wp1.y, xd[j]);
                    }
                }
                #pragma unroll
                for (int k = 0; k < 4; k++) {
                    float bA = sm.absh[s1p][r0 + 2 * k];
                    float bB = sm.absh[s1p][r0 + 2 * k + 1];
                    #pragma unroll
                    for (int j = 0; j < 4; j++) {
                        float lo, hi;
                        unpack2(acc2[k][j], lo, hi);
                        int off = tcv[j] * 28 + vv[j];
                        sm.CaCb[s1p][r0 + 2 * k][off]     = lo + bA;
                        sm.CaCb[s1p][r0 + 2 * k + 1][off] = hi + bB;
                    }
                }
            }
            __syncthreads();

            // Phase 2: warp-per-(s,tc); 5x5 lane grid; M -> smem
            {
                float S[5][5];
                #pragma unroll
                for (int i = 0; i < 5; i++)
                    #pragma unroll
                    for (int j = 0; j < 5; j++) S[i][j] = 0.f;

                #pragma unroll 4
                for (int ic = 0; ic < 16; ic++) {
                    float ca[5], cb[5];
                    #pragma unroll
                    for (int i = 0; i < 5; i++)
                        ca[i] = sm.CaCb[s2][ic][tcBase2 + a0 + i];
                    #pragma unroll
                    for (int j = 0; j < 5; j++)
                        cb[j] = sm.CaCb[s2][16 + ic][tcBase2 + b0 + j];
                    #pragma unroll
                    for (int i = 0; i < 5; i++)
                        #pragma unroll
                        for (int j = 0; j < 5; j++) S[i][j] += ca[i] * cb[j];
                }

                float rmax[5];
                #pragma unroll
                for (int i = 0; i < 5; i++) {
                    float m = -1e30f;
                    #pragma unroll
                    for (int j = 0; j < 5; j++) { S[i][j] *= 0.0625f; m = fmaxf(m, S[i][j]); }
                    rmax[i] = m;
                }
                #pragma unroll
                for (int k = 1; k < 5; k++) {
                    int src = ((cg2 + k) % 5) * 5 + rg2;
                    #pragma unroll
                    for (int i = 0; i < 5; i++)
                        rmax[i] = fmaxf(rmax[i], __shfl_sync(0xFFFFFFFFu, rmax[i], src));
                }

                float rsum[5];
                #pragma unroll
                for (int i = 0; i < 5; i++) {
                    float ssum = 0.f;
                    #pragma unroll
                    for (int j = 0; j < 5; j++) {
                        float e = fastexp(S[i][j] - rmax[i]);
                        S[i][j] = e;
                        ssum += e;
                    }
                    rsum[i] = ssum;
                }
                #pragma unroll
                for (int k = 1; k < 5; k++) {
                    int src = ((cg2 + k) % 5) * 5 + rg2;
                    #pragma unroll
                    for (int i = 0; i < 5; i++)
                        rsum[i] += __shfl_sync(0xFFFFFFFFu, rsum[i], src);
                }

                float colS[5];
                #pragma unroll
                for (int j = 0; j < 5; j++) colS[j] = 0.f;
                #pragma unroll
                for (int i = 0; i < 5; i++) {
                    float rinv = 1.f / rsum[i];
                    #pragma unroll
                    for (int j = 0; j < 5; j++) colS[j] += S[i][j] * rinv;
                }
                #pragma unroll
                for (int k = 1; k < 5; k++) {
                    int src = cg2 * 5 + (rg2 + k) % 5;
                    #pragma unroll
                    for (int j = 0; j < 5; j++)
                        colS[j] += __shfl_sync(0xFFFFFFFFu, colS[j], src);
                }

                if (lane < 25 && rg2 == 0) {
                    float* mp = &sm.Msm[s2][sc * SUBCOLS + tc2 * 25 + b0];
                    #pragma unroll
                    for (int j = 0; j < 5; j++)
                        mp[j] = colS[j] + sm.colA[s2][b0 + j];
                }
            }
        }
        __syncthreads();   // Msm complete

        // ---------- B-mainloop: 16 rows x 4 cols, fused s ----------
        if (tid < 300) {
            float ms[NS_][4];
            #pragma unroll
            for (int s = 0; s < NS_; s++)
                #pragma unroll
                for (int j = 0; j < 4; j++) ms[s][j] = sm.Msm[s][colB + j];

            ull acc2[8][4];   // [o-pair][col]
            #pragma unroll
            for (int k = 0; k < 8; k++)
                #pragma unroll
                for (int j = 0; j < 4; j++) acc2[k][j] = 0ull;

            #pragma unroll 2
            for (int c = 0; c < 64; c++) {
                float4 xv = *reinterpret_cast<const float4*>(&sm.xs[c][colB]);
                float xa[4] = {xv.x, xv.y, xv.z, xv.w};
                #pragma unroll
                for (int s = 0; s < NS_; s++) {
                    const ulonglong2* gp =
                        reinterpret_cast<const ulonglong2*>(&sm.GT[s][c][o0]);
                    ulonglong2 g01 = gp[0];
                    ulonglong2 g23 = gp[1];
                    ulonglong2 g45 = gp[2];
                    ulonglong2 g67 = gp[3];
                    ull xm[4];
                    #pragma unroll
                    for (int j = 0; j < 4; j++) xm[j] = dup2(xa[j] * ms[s][j]);
                    #pragma unroll
                    for (int j = 0; j < 4; j++) {
                        fma2(acc2[0][j], g01.x, xm[j]);
                        fma2(acc2[1][j], g01.y, xm[j]);
                        fma2(acc2[2][j], g23.x, xm[j]);
                        fma2(acc2[3][j], g23.y, xm[j]);
                        fma2(acc2[4][j], g45.x, xm[j]);
                        fma2(acc2[5][j], g45.y, xm[j]);
                        fma2(acc2[6][j], g67.x, xm[j]);
                        fma2(acc2[7][j], g67.y, xm[j]);
                    }
                }
            }

            // epilogue: BN + residual + ReLU
            #pragma unroll
            for (int k = 0; k < 8; k++) {
                int oa = o0 + 2 * k;
                int ob = oa + 1;
                float scA = sm.scArr[oa], shA = sm.shArr[oa];
                float scB = sm.scArr[ob], shB = sm.shArr[ob];
                float ra[4], rb[4];
                #pragma unroll
                for (int j = 0; j < 4; j++) unpack2(acc2[k][j], ra[j], rb[j]);
                float4 xrA = *reinterpret_cast<const float4*>(&sm.xs[oa][colB]);
                float4 xrB = *reinterpret_cast<const float4*>(&sm.xs[ob][colB]);
                float4 resA, resB;
                resA.x = fmaxf(ra[0] * scA + shA + xrA.x, 0.f);
                resA.y = fmaxf(ra[1] * scA + shA + xrA.y, 0.f);
                resA.z = fmaxf(ra[2] * scA + shA + xrA.z, 0.f);
                resA.w = fmaxf(ra[3] * scA + shA + xrA.w, 0.f);
                resB.x = fmaxf(rb[0] * scB + shB + xrB.x, 0.f);
                resB.y = fmaxf(rb[1] * scB + shB + xrB.y, 0.f);
                resB.z = fmaxf(rb[2] * scB + shB + xrB.z, 0.f);
                resB.w = fmaxf(rb[3] * scB + shB + xrB.w, 0.f);
                float* opA = out + (n * 64 + oa) * (T_ * V_) + t12 * V_ + colB;
                float* opB = out + (n * 64 + ob) * (T_ * V_) + t12 * V_ + colB;
                *reinterpret_cast<float4*>(opA) = resA;
                *reinterpret_cast<float4*>(opB) = resB;
            }
        }
    }
}

extern "C" void kernel_launch(void* const* d_in, const int* in_sizes, int n_in,
                              void* d_out, int out_size)
{
    const float* x        = (const float*)d_in[0];
    const float* A        = (const float*)d_in[1];
    const float* GA       = (const float*)d_in[2];
    const float* g_w      = (const float*)d_in[3];
    const float* g_b      = (const float*)d_in[4];
    const float* a_w      = (const float*)d_in[5];
    const float* a_b      = (const float*)d_in[6];
    const float* b_w      = (const float*)d_in[7];
    const float* b_b      = (const float*)d_in[8];
    const float* bn_gamma = (const float*)d_in[9];
    const float* bn_beta  = (const float*)d_in[10];
    const float* bn_mean  = (const float*)d_in[11];
    const float* bn_var   = (const float*)d_in[12];
    float* out = (float*)d_out;

    size_t smem = sizeof(SmemF);
    cudaFuncSetAttribute(tsagc_fused_kernel,
                         cudaFuncAttributeMaxDynamicSharedMemorySize, (int)smem);
    tsagc_fused_kernel<<<GRID_P, NT, smem>>>(
        x, A, GA, g_w, g_b, a_w, a_b, b_w, b_b,
        bn_gamma, bn_beta, bn_mean, bn_var, out);
}